// round 5
// baseline (speedup 1.0000x reference)
#include <cuda_runtime.h>
#include <cstdint>

// Sparsemax along dim=-1 for X[4096, 32000] fp32. Persistent-CTA (R2 topology)
// + L2 bulk prefetch lookahead:
//  - row j in registers (8 x float4/thread), single 128KB smem buffer holds
//    row j+1 via TMA (mbarrier), TMA issue for j+2 right after buffer frees.
//  - NEW: cp.async.bulk.prefetch.L2 pulls row j+3 into L2 every iteration,
//    so DRAM reads run ~2 rows ahead of consumption and the TMA smem fill
//    becomes an L2 hit (decouples row period from DRAM read latency/pacing).
//  - NEW: streaming stores (st.global.cs) keep output from evicting the
//    prefetched input in L2; max fused into the smem->reg copy.
//  - tau: support subset of {x > max-1} (~31 elems for N(0,1) rows), ballot
//    compaction + warp0 Newton; block-register-Newton fallback (rare rows).

#define NTHREADS 1024
#define NVEC     8
#define D        32000
#define D4       8000
#define ROWB     (D * 4)       // 128000 bytes per row
#define CSLOTS   64            // candidate slots per warp

__device__ __forceinline__ unsigned smem_u32(const void* p) {
    return (unsigned)__cvta_generic_to_shared(p);
}

__device__ __forceinline__ float warp_max_f(float v) {
    #pragma unroll
    for (int o = 16; o > 0; o >>= 1)
        v = fmaxf(v, __shfl_xor_sync(0xffffffffu, v, o));
    return v;
}

__device__ __forceinline__ void mbar_wait(unsigned mbar, unsigned ph) {
    asm volatile(
        "{\n\t"
        ".reg .pred P;\n\t"
        "WAIT_%=: \n\t"
        "mbarrier.try_wait.parity.acquire.cta.shared::cta.b64 P, [%0], %1, 0x989680;\n\t"
        "@P bra.uni DONE_%=;\n\t"
        "bra.uni WAIT_%=;\n\t"
        "DONE_%=: \n\t"
        "}\n\t" :: "r"(mbar), "r"(ph) : "memory");
}

__device__ __forceinline__ void bulk_prefetch_smem(unsigned dst_smem, const float* src,
                                                   unsigned bytes, unsigned mbar) {
    asm volatile("mbarrier.arrive.expect_tx.shared.b64 _, [%0], %1;"
                 :: "r"(mbar), "r"(bytes) : "memory");
    asm volatile("cp.async.bulk.shared::cluster.global.mbarrier::complete_tx::bytes "
                 "[%0], [%1], %2, [%3];"
                 :: "r"(dst_smem), "l"(src), "r"(bytes), "r"(mbar) : "memory");
}

__device__ __forceinline__ void bulk_prefetch_l2(const float* src, unsigned bytes) {
    asm volatile("cp.async.bulk.prefetch.L2.global [%0], %1;"
                 :: "l"(src), "r"(bytes) : "memory");
}

__global__ void __launch_bounds__(NTHREADS, 1)
sparsemax_kernel(const float* __restrict__ X, float* __restrict__ Y, int nrows)
{
    __shared__ float s_warpf[32];
    __shared__ int   s_warpcnt[32];
    __shared__ float s_bcast;
    __shared__ float s_tau;
    __shared__ int   s_of;
    __shared__ __align__(8) unsigned long long s_mbar;

    extern __shared__ float s_dyn[];
    float* s_buf  = s_dyn;        // 32000 floats = 128000 B prefetch buffer
    float* s_cand = s_dyn + D;    // 32*64 floats candidate regions

    const int t    = threadIdx.x;
    const int lane = t & 31;
    const int wid  = t >> 5;
    const int grid = gridDim.x;
    const unsigned mbar = smem_u32(&s_mbar);
    const float NINF = __int_as_float(0xff800000);

    if (t == 0)
        asm volatile("mbarrier.init.shared.b64 [%0], 1;" :: "r"(mbar) : "memory");
    __syncthreads();

    int row = blockIdx.x;
    if (row >= nrows) return;

    // ---- prologue: load row0 from global into regs (fused max) -------------
    float4 v[NVEC];
    float vmax = NINF;
    {
        const float4* src = reinterpret_cast<const float4*>(X) + (long long)row * D4;
        #pragma unroll
        for (int i = 0; i < NVEC - 1; i++) {
            v[i] = src[t + i * NTHREADS];
            vmax = fmaxf(vmax, fmaxf(fmaxf(v[i].x, v[i].y), fmaxf(v[i].z, v[i].w)));
        }
        if (t + (NVEC - 1) * NTHREADS < D4) {
            v[NVEC - 1] = src[t + (NVEC - 1) * NTHREADS];
            vmax = fmaxf(vmax, fmaxf(fmaxf(v[NVEC-1].x, v[NVEC-1].y),
                                     fmaxf(v[NVEC-1].z, v[NVEC-1].w)));
        } else {
            v[NVEC - 1] = make_float4(NINF, NINF, NINF, NINF);
        }
    }
    int next = row + grid;
    if (t == 0) {
        // warm L2 two rows ahead, then TMA row j+1 into smem
        if (next < nrows)                 bulk_prefetch_l2(X + (long long)next * D, ROWB);
        if (next + grid < nrows)          bulk_prefetch_l2(X + ((long long)next + grid) * D, ROWB);
        if (next < nrows)                 bulk_prefetch_smem(smem_u32(s_buf),
                                                X + (long long)next * D, ROWB, mbar);
    }
    unsigned ph = 0;

    for (;;) {
        // ---- keep DRAM reads running 3 rows ahead (L2 prefetch) ------------
        if (t == 0) {
            long long pf = (long long)row + 3LL * grid;
            if (pf < nrows) bulk_prefetch_l2(X + pf * D, ROWB);
        }

        // ---- block max (vmax carried from load/copy) ------------------------
        float wm = warp_max_f(vmax);
        if (lane == 0) s_warpf[wid] = wm;
        if (t == 0) s_of = 0;
        __syncthreads();                                   // B1
        if (wid == 0) {
            float m = warp_max_f(s_warpf[lane]);
            if (lane == 0) s_bcast = m;
        }
        __syncthreads();                                   // B2
        const float tau0 = s_bcast - 1.0f;

        // ---- per-warp ballot compaction of candidates (x > tau0) -----------
        {
            int cnt = 0;
            const unsigned lml = (1u << lane) - 1u;
            const int base = wid * CSLOTS;
            #pragma unroll
            for (int i = 0; i < NVEC; i++) {
                float xs[4] = {v[i].x, v[i].y, v[i].z, v[i].w};
                #pragma unroll
                for (int c = 0; c < 4; c++) {
                    float x = xs[c];
                    bool p = x > tau0;
                    unsigned m = __ballot_sync(0xffffffffu, p);
                    if (p) {
                        int pos = cnt + __popc(m & lml);
                        if (pos < CSLOTS) s_cand[base + pos] = x;
                    }
                    cnt += __popc(m);
                }
            }
            if (lane == 0) { s_warpcnt[wid] = cnt; if (cnt > CSLOTS) s_of = 1; }
        }
        __syncthreads();                                   // B3

        // ---- warp0 Newton on candidate list ---------------------------------
        if (wid == 0) {
            int n = s_warpcnt[lane]; if (n > CSLOTS) n = CSLOTS;
            const int base = lane * CSLOTS;
            float tt = tau0;
            for (int it = 0; it < 64; it++) {
                float s = 0.0f; int k = 0;
                for (int j = 0; j < n; j++) {
                    float c = s_cand[base + j];
                    if (c > tt) { s += c; k++; }
                }
                #pragma unroll
                for (int o = 16; o > 0; o >>= 1) {
                    s += __shfl_xor_sync(0xffffffffu, s, o);
                    k += __shfl_xor_sync(0xffffffffu, k, o);
                }
                float nt = (s - 1.0f) / (float)k;          // k>=1 (argmax active)
                if (nt == tt) break;
                tt = nt;
            }
            if (lane == 0) s_tau = tt;
        }
        __syncthreads();                                   // B4

        if (s_of) {
            // ---- fallback: block-wide Newton over registers (rare) ----------
            float tt = tau0;
            for (int it = 0; it < 64; it++) {
                float s = 0.0f; int k = 0;
                #pragma unroll
                for (int i = 0; i < NVEC; i++) {
                    if (v[i].x > tt) { s += v[i].x; k++; }
                    if (v[i].y > tt) { s += v[i].y; k++; }
                    if (v[i].z > tt) { s += v[i].z; k++; }
                    if (v[i].w > tt) { s += v[i].w; k++; }
                }
                #pragma unroll
                for (int o = 16; o > 0; o >>= 1) {
                    s += __shfl_xor_sync(0xffffffffu, s, o);
                    k += __shfl_xor_sync(0xffffffffu, k, o);
                }
                if (lane == 0) { s_warpf[wid] = s; s_warpcnt[wid] = k; }
                __syncthreads();
                if (t == 0) {
                    float S = 0.0f; int K = 0;
                    #pragma unroll
                    for (int w = 0; w < 32; w++) { S += s_warpf[w]; K += s_warpcnt[w]; }
                    s_bcast = (S - 1.0f) / (float)K;
                }
                __syncthreads();
                float nt = s_bcast;
                if (nt == tt) break;                        // uniform exit
                tt = nt;
            }
            if (t == 0) s_tau = tt;
            __syncthreads();
        }
        const float tau = s_tau;

        // ---- store output for this row (streaming hint) ---------------------
        {
            float4* dst = reinterpret_cast<float4*>(Y) + (long long)row * D4;
            #pragma unroll
            for (int i = 0; i < NVEC; i++) {
                int idx = t + i * NTHREADS;
                if (i < NVEC - 1 || idx < D4) {
                    float4 o;
                    o.x = fmaxf(v[i].x - tau, 0.0f);
                    o.y = fmaxf(v[i].y - tau, 0.0f);
                    o.z = fmaxf(v[i].z - tau, 0.0f);
                    o.w = fmaxf(v[i].w - tau, 0.0f);
                    __stcs(dst + idx, o);
                }
            }
        }

        if (next >= nrows) break;

        // ---- wait prefetch, copy smem -> regs (fused max), issue next -------
        mbar_wait(mbar, ph);
        ph ^= 1u;
        vmax = NINF;
        {
            const float4* sb4 = reinterpret_cast<const float4*>(s_buf);
            #pragma unroll
            for (int i = 0; i < NVEC - 1; i++) {
                v[i] = sb4[t + i * NTHREADS];
                vmax = fmaxf(vmax, fmaxf(fmaxf(v[i].x, v[i].y), fmaxf(v[i].z, v[i].w)));
            }
            if (t + (NVEC - 1) * NTHREADS < D4) {
                v[NVEC - 1] = sb4[t + (NVEC - 1) * NTHREADS];
                vmax = fmaxf(vmax, fmaxf(fmaxf(v[NVEC-1].x, v[NVEC-1].y),
                                         fmaxf(v[NVEC-1].z, v[NVEC-1].w)));
            }
            // tail lanes keep -inf padding from prologue
        }
        __syncthreads();                                   // B5: s_buf free
        int nn = next + grid;
        if (t == 0 && nn < nrows)
            bulk_prefetch_smem(smem_u32(s_buf), X + (long long)nn * D, ROWB, mbar);
        row = next;
        next = nn;
    }
}

extern "C" void kernel_launch(void* const* d_in, const int* in_sizes, int n_in,
                              void* d_out, int out_size)
{
    const float* X = (const float*)d_in[0];
    float* Y = (float*)d_out;
    int rows = in_sizes[0] / D;                 // 4096

    int sms = 148;
    cudaDeviceGetAttribute(&sms, cudaDevAttrMultiProcessorCount, 0);
    int grid = (rows < sms) ? rows : sms;       // persistent: one CTA per SM

    size_t dyn = (size_t)(D + 32 * CSLOTS) * sizeof(float);   // 136192 B
    cudaFuncSetAttribute(sparsemax_kernel,
                         cudaFuncAttributeMaxDynamicSharedMemorySize, (int)dyn);
    sparsemax_kernel<<<grid, NTHREADS, dyn>>>(X, Y, rows);
}

// round 6
// speedup vs baseline: 1.2927x; 1.2927x over previous
#include <cuda_runtime.h>
#include <cstdint>

// Sparsemax along dim=-1 for X[4096, 32000] fp32. Persistent-CTA (R2 topology,
// best known: 186.6us) + minimal deltas:
//  - fused max into the global load / smem->reg copy (removes one serial pass)
//  - L2 bulk prefetch with ~1-iteration lead (row j+2 prefetched at top of
//    compute for row j; its TMA issues one iteration later). Resident
//    lookahead ~19MB across 152 CTAs -> survives L2, decouples the TMA wait
//    from DRAM latency without re-read traffic (R5's 3-row lead thrashed).
//  - single 128KB smem buffer, TMA for row j+2 issued right after the copy
//    frees the buffer (proven R2 ordering; chunking regressed twice).
//  - tau: support subset of {x > max-1} (~31 elems), ballot compaction +
//    warp0 Newton; block-register-Newton fallback for adversarial rows.

#define NTHREADS 1024
#define NVEC     8
#define D        32000
#define D4       8000
#define ROWB     (D * 4)       // 128000 bytes per row
#define CSLOTS   64            // candidate slots per warp

__device__ __forceinline__ unsigned smem_u32(const void* p) {
    return (unsigned)__cvta_generic_to_shared(p);
}

__device__ __forceinline__ float warp_max_f(float v) {
    #pragma unroll
    for (int o = 16; o > 0; o >>= 1)
        v = fmaxf(v, __shfl_xor_sync(0xffffffffu, v, o));
    return v;
}

__device__ __forceinline__ void mbar_wait(unsigned mbar, unsigned ph) {
    asm volatile(
        "{\n\t"
        ".reg .pred P;\n\t"
        "WAIT_%=: \n\t"
        "mbarrier.try_wait.parity.acquire.cta.shared::cta.b64 P, [%0], %1, 0x989680;\n\t"
        "@P bra.uni DONE_%=;\n\t"
        "bra.uni WAIT_%=;\n\t"
        "DONE_%=: \n\t"
        "}\n\t" :: "r"(mbar), "r"(ph) : "memory");
}

__device__ __forceinline__ void bulk_prefetch_smem(unsigned dst_smem, const float* src,
                                                   unsigned bytes, unsigned mbar) {
    asm volatile("mbarrier.arrive.expect_tx.shared.b64 _, [%0], %1;"
                 :: "r"(mbar), "r"(bytes) : "memory");
    asm volatile("cp.async.bulk.shared::cluster.global.mbarrier::complete_tx::bytes "
                 "[%0], [%1], %2, [%3];"
                 :: "r"(dst_smem), "l"(src), "r"(bytes), "r"(mbar) : "memory");
}

__device__ __forceinline__ void bulk_prefetch_l2(const float* src, unsigned bytes) {
    asm volatile("cp.async.bulk.prefetch.L2.global [%0], %1;"
                 :: "l"(src), "r"(bytes) : "memory");
}

__global__ void __launch_bounds__(NTHREADS, 1)
sparsemax_kernel(const float* __restrict__ X, float* __restrict__ Y, int nrows)
{
    __shared__ float s_warpf[32];
    __shared__ int   s_warpcnt[32];
    __shared__ float s_bcast;
    __shared__ float s_tau;
    __shared__ int   s_of;
    __shared__ __align__(8) unsigned long long s_mbar;

    extern __shared__ float s_dyn[];
    float* s_buf  = s_dyn;        // 32000 floats = 128000 B prefetch buffer
    float* s_cand = s_dyn + D;    // 32*64 floats candidate regions

    const int t    = threadIdx.x;
    const int lane = t & 31;
    const int wid  = t >> 5;
    const int grid = gridDim.x;
    const unsigned mbar = smem_u32(&s_mbar);
    const float NINF = __int_as_float(0xff800000);

    if (t == 0)
        asm volatile("mbarrier.init.shared.b64 [%0], 1;" :: "r"(mbar) : "memory");
    __syncthreads();

    int row = blockIdx.x;
    if (row >= nrows) return;

    // ---- prologue: warm L2 for row j+1, load row0 into regs (fused max) ----
    if (t == 0 && row + grid < nrows)
        bulk_prefetch_l2(X + ((long long)row + grid) * D, ROWB);

    float4 v[NVEC];
    float vmax = NINF;
    {
        const float4* src = reinterpret_cast<const float4*>(X) + (long long)row * D4;
        #pragma unroll
        for (int i = 0; i < NVEC - 1; i++) {
            v[i] = src[t + i * NTHREADS];
            vmax = fmaxf(vmax, fmaxf(fmaxf(v[i].x, v[i].y), fmaxf(v[i].z, v[i].w)));
        }
        if (t + (NVEC - 1) * NTHREADS < D4) {
            v[NVEC - 1] = src[t + (NVEC - 1) * NTHREADS];
            vmax = fmaxf(vmax, fmaxf(fmaxf(v[NVEC-1].x, v[NVEC-1].y),
                                     fmaxf(v[NVEC-1].z, v[NVEC-1].w)));
        } else {
            v[NVEC - 1] = make_float4(NINF, NINF, NINF, NINF);
        }
    }
    int next = row + grid;
    if (t == 0 && next < nrows)
        bulk_prefetch_smem(smem_u32(s_buf), X + (long long)next * D, ROWB, mbar);
    unsigned ph = 0;

    for (;;) {
        // ---- L2 prefetch row j+2 (lead ~= 1 iteration before its TMA) -------
        if (t == 0) {
            long long pf = (long long)row + 2LL * grid;
            if (pf < nrows) bulk_prefetch_l2(X + pf * D, ROWB);
        }

        // ---- block max (vmax carried from load/copy) -------------------------
        float wm = warp_max_f(vmax);
        if (lane == 0) s_warpf[wid] = wm;
        if (t == 0) s_of = 0;
        __syncthreads();                                   // B1
        if (wid == 0) {
            float m = warp_max_f(s_warpf[lane]);
            if (lane == 0) s_bcast = m;
        }
        __syncthreads();                                   // B2
        const float tau0 = s_bcast - 1.0f;

        // ---- per-warp ballot compaction of candidates (x > tau0) ------------
        {
            int cnt = 0;
            const unsigned lml = (1u << lane) - 1u;
            const int base = wid * CSLOTS;
            #pragma unroll
            for (int i = 0; i < NVEC; i++) {
                float xs[4] = {v[i].x, v[i].y, v[i].z, v[i].w};
                #pragma unroll
                for (int c = 0; c < 4; c++) {
                    float x = xs[c];
                    bool p = x > tau0;
                    unsigned m = __ballot_sync(0xffffffffu, p);
                    if (p) {
                        int pos = cnt + __popc(m & lml);
                        if (pos < CSLOTS) s_cand[base + pos] = x;
                    }
                    cnt += __popc(m);
                }
            }
            if (lane == 0) { s_warpcnt[wid] = cnt; if (cnt > CSLOTS) s_of = 1; }
        }
        __syncthreads();                                   // B3

        // ---- warp0 Newton on candidate list ----------------------------------
        if (wid == 0) {
            int n = s_warpcnt[lane]; if (n > CSLOTS) n = CSLOTS;
            const int base = lane * CSLOTS;
            float tt = tau0;
            for (int it = 0; it < 64; it++) {
                float s = 0.0f; int k = 0;
                for (int j = 0; j < n; j++) {
                    float c = s_cand[base + j];
                    if (c > tt) { s += c; k++; }
                }
                #pragma unroll
                for (int o = 16; o > 0; o >>= 1) {
                    s += __shfl_xor_sync(0xffffffffu, s, o);
                    k += __shfl_xor_sync(0xffffffffu, k, o);
                }
                float nt = (s - 1.0f) / (float)k;          // k>=1 (argmax active)
                if (nt == tt) break;
                tt = nt;
            }
            if (lane == 0) s_tau = tt;
        }
        __syncthreads();                                   // B4

        if (s_of) {
            // ---- fallback: block-wide Newton over registers (rare) -----------
            float tt = tau0;
            for (int it = 0; it < 64; it++) {
                float s = 0.0f; int k = 0;
                #pragma unroll
                for (int i = 0; i < NVEC; i++) {
                    if (v[i].x > tt) { s += v[i].x; k++; }
                    if (v[i].y > tt) { s += v[i].y; k++; }
                    if (v[i].z > tt) { s += v[i].z; k++; }
                    if (v[i].w > tt) { s += v[i].w; k++; }
                }
                #pragma unroll
                for (int o = 16; o > 0; o >>= 1) {
                    s += __shfl_xor_sync(0xffffffffu, s, o);
                    k += __shfl_xor_sync(0xffffffffu, k, o);
                }
                if (lane == 0) { s_warpf[wid] = s; s_warpcnt[wid] = k; }
                __syncthreads();
                if (t == 0) {
                    float S = 0.0f; int K = 0;
                    #pragma unroll
                    for (int w = 0; w < 32; w++) { S += s_warpf[w]; K += s_warpcnt[w]; }
                    s_bcast = (S - 1.0f) / (float)K;
                }
                __syncthreads();
                float nt = s_bcast;
                if (nt == tt) break;                        // uniform exit
                tt = nt;
            }
            if (t == 0) s_tau = tt;
            __syncthreads();
        }
        const float tau = s_tau;

        // ---- store output for this row ---------------------------------------
        {
            float4* dst = reinterpret_cast<float4*>(Y) + (long long)row * D4;
            #pragma unroll
            for (int i = 0; i < NVEC; i++) {
                int idx = t + i * NTHREADS;
                if (i < NVEC - 1 || idx < D4) {
                    float4 o;
                    o.x = fmaxf(v[i].x - tau, 0.0f);
                    o.y = fmaxf(v[i].y - tau, 0.0f);
                    o.z = fmaxf(v[i].z - tau, 0.0f);
                    o.w = fmaxf(v[i].w - tau, 0.0f);
                    dst[idx] = o;
                }
            }
        }

        if (next >= nrows) break;

        // ---- wait prefetch, copy smem -> regs (fused max), issue next TMA ----
        mbar_wait(mbar, ph);
        ph ^= 1u;
        vmax = NINF;
        {
            const float4* sb4 = reinterpret_cast<const float4*>(s_buf);
            #pragma unroll
            for (int i = 0; i < NVEC - 1; i++) {
                v[i] = sb4[t + i * NTHREADS];
                vmax = fmaxf(vmax, fmaxf(fmaxf(v[i].x, v[i].y), fmaxf(v[i].z, v[i].w)));
            }
            if (t + (NVEC - 1) * NTHREADS < D4) {
                v[NVEC - 1] = sb4[t + (NVEC - 1) * NTHREADS];
                vmax = fmaxf(vmax, fmaxf(fmaxf(v[NVEC-1].x, v[NVEC-1].y),
                                         fmaxf(v[NVEC-1].z, v[NVEC-1].w)));
            }
            // tail lanes keep -inf padding from prologue
        }
        __syncthreads();                                   // B5: s_buf free
        int nn = next + grid;
        if (t == 0 && nn < nrows)
            bulk_prefetch_smem(smem_u32(s_buf), X + (long long)nn * D, ROWB, mbar);
        row = next;
        next = nn;
    }
}

extern "C" void kernel_launch(void* const* d_in, const int* in_sizes, int n_in,
                              void* d_out, int out_size)
{
    const float* X = (const float*)d_in[0];
    float* Y = (float*)d_out;
    int rows = in_sizes[0] / D;                 // 4096

    int sms = 148;
    cudaDeviceGetAttribute(&sms, cudaDevAttrMultiProcessorCount, 0);
    int grid = (rows < sms) ? rows : sms;       // persistent: one CTA per SM

    size_t dyn = (size_t)(D + 32 * CSLOTS) * sizeof(float);   // 136192 B
    cudaFuncSetAttribute(sparsemax_kernel,
                         cudaFuncAttributeMaxDynamicSharedMemorySize, (int)dyn);
    sparsemax_kernel<<<grid, NTHREADS, dyn>>>(X, Y, rows);
}

// round 7
// speedup vs baseline: 1.3350x; 1.0328x over previous
#include <cuda_runtime.h>
#include <cstdint>

// Sparsemax along dim=-1 for X[4096, 32000] fp32. Persistent-CTA (R2 topology)
// with ROTATED loop: tau is solved one row AHEAD, so every iteration begins by
// issuing stores (write stream busy during the TMA wait + copy + next solve).
//   iter j:  store(j; tau precomputed) -> wait TMA(j+1) -> copy+max(j+1)
//            -> compact -> issue TMA(j+2) -> Newton tau(j+1)
// No L2 prefetch, no chunking (both measured negative in R3-R6).
//  - row in registers (8 x float4/thread), single 128KB smem TMA buffer.
//  - tau: support subset of {x > max-1} (~31 elems), ballot compaction +
//    warp0 Newton; block-register-Newton fallback for adversarial rows.

#define NTHREADS 1024
#define NVEC     8
#define D        32000
#define D4       8000
#define ROWB     (D * 4)       // 128000 bytes per row
#define CSLOTS   64            // candidate slots per warp

__device__ __forceinline__ unsigned smem_u32(const void* p) {
    return (unsigned)__cvta_generic_to_shared(p);
}

__device__ __forceinline__ float warp_max_f(float v) {
    #pragma unroll
    for (int o = 16; o > 0; o >>= 1)
        v = fmaxf(v, __shfl_xor_sync(0xffffffffu, v, o));
    return v;
}

__device__ __forceinline__ void mbar_wait(unsigned mbar, unsigned ph) {
    asm volatile(
        "{\n\t"
        ".reg .pred P;\n\t"
        "WAIT_%=: \n\t"
        "mbarrier.try_wait.parity.acquire.cta.shared::cta.b64 P, [%0], %1, 0x989680;\n\t"
        "@P bra.uni DONE_%=;\n\t"
        "bra.uni WAIT_%=;\n\t"
        "DONE_%=: \n\t"
        "}\n\t" :: "r"(mbar), "r"(ph) : "memory");
}

__device__ __forceinline__ void bulk_prefetch_smem(unsigned dst_smem, const float* src,
                                                   unsigned bytes, unsigned mbar) {
    asm volatile("mbarrier.arrive.expect_tx.shared.b64 _, [%0], %1;"
                 :: "r"(mbar), "r"(bytes) : "memory");
    asm volatile("cp.async.bulk.shared::cluster.global.mbarrier::complete_tx::bytes "
                 "[%0], [%1], %2, [%3];"
                 :: "r"(dst_smem), "l"(src), "r"(bytes), "r"(mbar) : "memory");
}

__global__ void __launch_bounds__(NTHREADS, 1)
sparsemax_kernel(const float* __restrict__ X, float* __restrict__ Y, int nrows)
{
    __shared__ float s_warpf[32];
    __shared__ int   s_warpcnt[32];
    __shared__ float s_bcast;
    __shared__ float s_tau;
    __shared__ int   s_of;
    __shared__ __align__(8) unsigned long long s_mbar;

    extern __shared__ float s_dyn[];
    float* s_buf  = s_dyn;        // 32000 floats = 128000 B TMA buffer
    float* s_cand = s_dyn + D;    // 32*64 floats candidate regions

    const int t    = threadIdx.x;
    const int lane = t & 31;
    const int wid  = t >> 5;
    const int grid = gridDim.x;
    const unsigned mbar = smem_u32(&s_mbar);
    const float NINF = __int_as_float(0xff800000);

    if (t == 0)
        asm volatile("mbarrier.init.shared.b64 [%0], 1;" :: "r"(mbar) : "memory");
    __syncthreads();

    int row = blockIdx.x;
    if (row >= nrows) return;
    int next = row + grid;

    float4 v[NVEC];
    float vmax = NINF;

    // ---- prologue: load row0 from global (fused max), start TMA row1 -------
    {
        const float4* src = reinterpret_cast<const float4*>(X) + (long long)row * D4;
        #pragma unroll
        for (int i = 0; i < NVEC - 1; i++) {
            v[i] = src[t + i * NTHREADS];
            vmax = fmaxf(vmax, fmaxf(fmaxf(v[i].x, v[i].y), fmaxf(v[i].z, v[i].w)));
        }
        if (t + (NVEC - 1) * NTHREADS < D4) {
            v[NVEC - 1] = src[t + (NVEC - 1) * NTHREADS];
            vmax = fmaxf(vmax, fmaxf(fmaxf(v[NVEC-1].x, v[NVEC-1].y),
                                     fmaxf(v[NVEC-1].z, v[NVEC-1].w)));
        } else {
            v[NVEC - 1] = make_float4(NINF, NINF, NINF, NINF);
        }
    }
    if (t == 0 && next < nrows)
        bulk_prefetch_smem(smem_u32(s_buf), X + (long long)next * D, ROWB, mbar);
    unsigned ph = 0;
    float tau;

    // =====================  solve tau for the row in regs  ==================
    // (emitted once via a loop-rotation: solve happens at the END of each
    //  iteration for the NEXT row; here for row 0 before entering the loop)
    #define SOLVE_TAU()                                                        \
    do {                                                                       \
        float wm = warp_max_f(vmax);                                           \
        if (lane == 0) s_warpf[wid] = wm;                                      \
        if (t == 0) s_of = 0;                                                  \
        __syncthreads();                                                       \
        if (wid == 0) {                                                        \
            float m = warp_max_f(s_warpf[lane]);                               \
            if (lane == 0) s_bcast = m;                                        \
        }                                                                      \
        __syncthreads();                                                       \
        const float tau0 = s_bcast - 1.0f;                                     \
        {                                                                      \
            int cnt = 0;                                                       \
            const unsigned lml = (1u << lane) - 1u;                            \
            const int base = wid * CSLOTS;                                     \
            _Pragma("unroll")                                                  \
            for (int i = 0; i < NVEC; i++) {                                   \
                float xs[4] = {v[i].x, v[i].y, v[i].z, v[i].w};                \
                _Pragma("unroll")                                              \
                for (int c = 0; c < 4; c++) {                                  \
                    float x = xs[c];                                           \
                    bool p = x > tau0;                                         \
                    unsigned m = __ballot_sync(0xffffffffu, p);                \
                    if (p) {                                                   \
                        int pos = cnt + __popc(m & lml);                       \
                        if (pos < CSLOTS) s_cand[base + pos] = x;              \
                    }                                                          \
                    cnt += __popc(m);                                          \
                }                                                              \
            }                                                                  \
            if (lane == 0) { s_warpcnt[wid] = cnt; if (cnt > CSLOTS) s_of = 1; } \
        }                                                                      \
        __syncthreads();                                                       \
        if (wid == 0) {                                                        \
            int n = s_warpcnt[lane]; if (n > CSLOTS) n = CSLOTS;               \
            const int base = lane * CSLOTS;                                    \
            float tt = tau0;                                                   \
            for (int it = 0; it < 64; it++) {                                  \
                float s = 0.0f; int k = 0;                                     \
                for (int j2 = 0; j2 < n; j2++) {                               \
                    float c = s_cand[base + j2];                               \
                    if (c > tt) { s += c; k++; }                               \
                }                                                              \
                _Pragma("unroll")                                              \
                for (int o = 16; o > 0; o >>= 1) {                             \
                    s += __shfl_xor_sync(0xffffffffu, s, o);                   \
                    k += __shfl_xor_sync(0xffffffffu, k, o);                   \
                }                                                              \
                float nt = (s - 1.0f) / (float)k;                              \
                if (nt == tt) break;                                           \
                tt = nt;                                                       \
            }                                                                  \
            if (lane == 0) s_tau = tt;                                         \
        }                                                                      \
        __syncthreads();                                                       \
        if (s_of) {                                                            \
            float tt = tau0;                                                   \
            for (int it = 0; it < 64; it++) {                                  \
                float s = 0.0f; int k = 0;                                     \
                _Pragma("unroll")                                              \
                for (int i = 0; i < NVEC; i++) {                               \
                    if (v[i].x > tt) { s += v[i].x; k++; }                     \
                    if (v[i].y > tt) { s += v[i].y; k++; }                     \
                    if (v[i].z > tt) { s += v[i].z; k++; }                     \
                    if (v[i].w > tt) { s += v[i].w; k++; }                     \
                }                                                              \
                _Pragma("unroll")                                              \
                for (int o = 16; o > 0; o >>= 1) {                             \
                    s += __shfl_xor_sync(0xffffffffu, s, o);                   \
                    k += __shfl_xor_sync(0xffffffffu, k, o);                   \
                }                                                              \
                if (lane == 0) { s_warpf[wid] = s; s_warpcnt[wid] = k; }       \
                __syncthreads();                                               \
                if (t == 0) {                                                  \
                    float S = 0.0f; int K = 0;                                 \
                    _Pragma("unroll")                                          \
                    for (int w = 0; w < 32; w++) { S += s_warpf[w]; K += s_warpcnt[w]; } \
                    s_bcast = (S - 1.0f) / (float)K;                           \
                }                                                              \
                __syncthreads();                                               \
                float nt = s_bcast;                                            \
                if (nt == tt) break;                                           \
                tt = nt;                                                       \
            }                                                                  \
            if (t == 0) s_tau = tt;                                            \
            __syncthreads();                                                   \
        }                                                                      \
        tau = s_tau;                                                           \
    } while (0)

    SOLVE_TAU();   // tau for row 0

    for (;;) {
        // ---- 1) issue ALL stores for current row (tau precomputed) ---------
        {
            float4* dst = reinterpret_cast<float4*>(Y) + (long long)row * D4;
            #pragma unroll
            for (int i = 0; i < NVEC; i++) {
                int idx = t + i * NTHREADS;
                if (i < NVEC - 1 || idx < D4) {
                    float4 o;
                    o.x = fmaxf(v[i].x - tau, 0.0f);
                    o.y = fmaxf(v[i].y - tau, 0.0f);
                    o.z = fmaxf(v[i].z - tau, 0.0f);
                    o.w = fmaxf(v[i].w - tau, 0.0f);
                    dst[idx] = o;
                }
            }
        }

        if (next >= nrows) break;

        // ---- 2) wait TMA(next), copy smem -> regs with fused max -----------
        mbar_wait(mbar, ph);
        ph ^= 1u;
        vmax = NINF;
        {
            const float4* sb4 = reinterpret_cast<const float4*>(s_buf);
            #pragma unroll
            for (int i = 0; i < NVEC - 1; i++) {
                v[i] = sb4[t + i * NTHREADS];
                vmax = fmaxf(vmax, fmaxf(fmaxf(v[i].x, v[i].y), fmaxf(v[i].z, v[i].w)));
            }
            if (t + (NVEC - 1) * NTHREADS < D4) {
                v[NVEC - 1] = sb4[t + (NVEC - 1) * NTHREADS];
                vmax = fmaxf(vmax, fmaxf(fmaxf(v[NVEC-1].x, v[NVEC-1].y),
                                         fmaxf(v[NVEC-1].z, v[NVEC-1].w)));
            }
            // tail lanes keep -inf padding from prologue
        }
        __syncthreads();            // buffer consumed by all warps

        // ---- 3) immediately re-issue TMA for row next+grid -----------------
        {
            int nn = next + grid;
            if (t == 0 && nn < nrows)
                bulk_prefetch_smem(smem_u32(s_buf), X + (long long)nn * D, ROWB, mbar);
            row = next;
            next = nn;
        }

        // ---- 4) solve tau for the new row (overlaps store drain + TMA) -----
        SOLVE_TAU();
    }
}

extern "C" void kernel_launch(void* const* d_in, const int* in_sizes, int n_in,
                              void* d_out, int out_size)
{
    const float* X = (const float*)d_in[0];
    float* Y = (float*)d_out;
    int rows = in_sizes[0] / D;                 // 4096

    int sms = 148;
    cudaDeviceGetAttribute(&sms, cudaDevAttrMultiProcessorCount, 0);
    int grid = (rows < sms) ? rows : sms;       // persistent: one CTA per SM

    size_t dyn = (size_t)(D + 32 * CSLOTS) * sizeof(float);   // 136192 B
    cudaFuncSetAttribute(sparsemax_kernel,
                         cudaFuncAttributeMaxDynamicSharedMemorySize, (int)dyn);
    sparsemax_kernel<<<grid, NTHREADS, dyn>>>(X, Y, rows);
}